// round 13
// baseline (speedup 1.0000x reference)
#include <cuda_runtime.h>
#include <cuda_bf16.h>
#include <cstdint>
#include <math.h>

#define BDIM   16384
#define IN_DIM 4096
#define H1D    128
#define H2D    64
#define LAT    32
#define NREPS  3
#define SROW   80        // padded smem row stride (bytes) for 32 bf16 = 64B data
#define MTILE  112       // gemm1 CTA m-tile: 7 x m16, grid 147 = one full wave on 148 SMs

// ---------------------------------------------------------------------------
// Scratch (__device__ globals: allocation-free rule)
// ---------------------------------------------------------------------------
__device__ float g_h1[(size_t)BDIM * H1D];                            // 8 MB
__device__ __align__(16) __nv_bfloat16 g_q_h[(size_t)BDIM * LAT];
__device__ __align__(16) __nv_bfloat16 g_q_l[(size_t)BDIM * LAT];
__device__ __align__(16) __nv_bfloat16 g_W1t_h[(size_t)H1D * IN_DIM]; // W1^T [n][k]
__device__ __align__(16) __nv_bfloat16 g_W1t_l[(size_t)H1D * IN_DIM];
__device__ __align__(16) __nv_bfloat16 g_Wdt_h[(size_t)IN_DIM * LAT]; // Wd^T [n][k]
__device__ __align__(16) __nv_bfloat16 g_Wdt_l[(size_t)IN_DIM * LAT];

// ---------------------------------------------------------------------------
// Helpers (baseline PTX only: ldmatrix + mma.sync, sm_80-compatible)
// ---------------------------------------------------------------------------
__device__ __forceinline__ uint32_t smem_u32(const void* p) {
    uint32_t a;
    asm("{ .reg .u64 t; cvta.to.shared.u64 t, %1; cvt.u32.u64 %0, t; }" : "=r"(a) : "l"(p));
    return a;
}
__device__ __forceinline__ void ldsm_x4(uint32_t* r, uint32_t addr) {
    asm volatile("ldmatrix.sync.aligned.m8n8.x4.shared.b16 {%0,%1,%2,%3}, [%4];"
                 : "=r"(r[0]), "=r"(r[1]), "=r"(r[2]), "=r"(r[3]) : "r"(addr));
}
__device__ __forceinline__ void ldsm_x2(uint32_t* r, uint32_t addr) {
    asm volatile("ldmatrix.sync.aligned.m8n8.x2.shared.b16 {%0,%1}, [%2];"
                 : "=r"(r[0]), "=r"(r[1]) : "r"(addr));
}
__device__ __forceinline__ void mma16816(float* c, const uint32_t* a, const uint32_t* b) {
    asm volatile("mma.sync.aligned.m16n8k16.row.col.f32.bf16.bf16.f32 "
                 "{%0,%1,%2,%3}, {%4,%5,%6,%7}, {%8,%9}, {%0,%1,%2,%3};"
                 : "+f"(c[0]), "+f"(c[1]), "+f"(c[2]), "+f"(c[3])
                 : "r"(a[0]), "r"(a[1]), "r"(a[2]), "r"(a[3]), "r"(b[0]), "r"(b[1]));
}
__device__ __forceinline__ uint32_t pack_bf16x2(__nv_bfloat16 a, __nv_bfloat16 b) {
    return (uint32_t)__bfloat16_as_ushort(a) | ((uint32_t)__bfloat16_as_ushort(b) << 16);
}
__device__ __forceinline__ void split_bf16(float v, __nv_bfloat16& hi, __nv_bfloat16& lo) {
    hi = __float2bfloat16_rn(v);
    lo = __float2bfloat16_rn(v - __bfloat162float(hi));
}

// ---------------------------------------------------------------------------
// Merged prep: y<4 -> W1 transpose+split tiles; y==4 -> Wd transpose+split.
// ---------------------------------------------------------------------------
__global__ void k_prep(const float* __restrict__ W1, const float* __restrict__ Wd) {
    __shared__ float t[32][33];
    const int tx = threadIdx.x, ty = threadIdx.y;   // (32, 8)
    if (blockIdx.y < 4) {
        const int k0 = blockIdx.x * 32, n0 = blockIdx.y * 32;
        #pragma unroll
        for (int i = 0; i < 4; i++)
            t[ty + 8 * i][tx] = W1[(size_t)(k0 + ty + 8 * i) * H1D + n0 + tx];
        __syncthreads();
        #pragma unroll
        for (int i = 0; i < 4; i++) {
            const int n = n0 + ty + 8 * i, k = k0 + tx;
            __nv_bfloat16 h, l;
            split_bf16(t[tx][ty + 8 * i], h, l);
            g_W1t_h[(size_t)n * IN_DIM + k] = h;
            g_W1t_l[(size_t)n * IN_DIM + k] = l;
        }
    } else {
        const int n0 = blockIdx.x * 32;
        #pragma unroll
        for (int i = 0; i < 4; i++)
            t[ty + 8 * i][tx] = Wd[(size_t)(ty + 8 * i) * IN_DIM + n0 + tx];
        __syncthreads();
        #pragma unroll
        for (int i = 0; i < 4; i++) {
            const int n = n0 + ty + 8 * i, k = tx;
            __nv_bfloat16 h, l;
            split_bf16(t[tx][ty + 8 * i], h, l);
            g_Wdt_h[(size_t)n * LAT + k] = h;
            g_Wdt_l[(size_t)n * LAT + k] = l;
        }
    }
}

// ---------------------------------------------------------------------------
// GEMM1 (mma.sync): h1 = relu(x @ W1 + b1)
// CTA tile 112x128 (7 m16-tiles: wm0->4, wm1->3), BK=32, 8 warps, grid 147
// = exactly one wave on 148 SMs.  Loop body identical to the R5 structure.
// ---------------------------------------------------------------------------
__global__ __launch_bounds__(256) void k_gemm1_mma(const float* __restrict__ x,
                                                   const float* __restrict__ b1)
{
    __shared__ __align__(128) char sm[(MTILE + MTILE + 128 + 128) * SROW];  // Ah Al Bh Bl
    char* sAh = sm;
    char* sAl = sm + MTILE * SROW;
    char* sBh = sm + 2 * MTILE * SROW;
    char* sBl = sm + (2 * MTILE + 128) * SROW;
    const uint32_t uAh = smem_u32(sAh), uAl = smem_u32(sAl);
    const uint32_t uBh = smem_u32(sBh), uBl = smem_u32(sBl);

    const int tid  = threadIdx.x;
    const int lane = tid & 31, wid = tid >> 5;
    const int wm = wid >> 2, wn = wid & 3;         // warp grid 2(m) x 4(n)
    const int r = tid >> 1, h = tid & 1;           // load role: row, k-half
    const int row0 = blockIdx.x * MTILE;
    const int nim  = wm ? 3 : 4;                   // m16-tiles this warp owns
    const int it0  = wm ? 4 : 0;                   // first m16-tile index

    float acc[4][4][4];
    #pragma unroll
    for (int im = 0; im < 4; im++)
        #pragma unroll
        for (int in = 0; in < 4; in++)
            #pragma unroll
            for (int j = 0; j < 4; j++) acc[im][in][j] = 0.f;

    const int rowA = min(row0 + r, BDIM - 1);      // clamp OOB rows (last CTA)
    const float*         xp  = &x[(size_t)rowA * IN_DIM + h * 16];
    const __nv_bfloat16* wph = &g_W1t_h[(size_t)r * IN_DIM + h * 16];
    const __nv_bfloat16* wpl = &g_W1t_l[(size_t)r * IN_DIM + h * 16];
    const bool doA = (r < MTILE);

    // prefetch iter 0
    float4 xa[4]; uint4 wbh[2], wbl[2];
    if (doA) {
        #pragma unroll
        for (int j = 0; j < 4; j++) xa[j] = *(const float4*)(xp + j * 4);
    }
    wbh[0] = *(const uint4*)wph; wbh[1] = *(const uint4*)(wph + 8);
    wbl[0] = *(const uint4*)wpl; wbl[1] = *(const uint4*)(wpl + 8);

    const uint32_t sts = (uint32_t)(r * SROW + h * 32);

    for (int i = 0; i < IN_DIM / 32; ++i) {
        // convert + STS of current tile
        if (doA) {
            uint32_t hh[8], ll[8];
            #pragma unroll
            for (int j = 0; j < 4; j++) {
                __nv_bfloat16 h0, l0, h1_, l1, h2, l2, h3, l3;
                split_bf16(xa[j].x, h0, l0); split_bf16(xa[j].y, h1_, l1);
                split_bf16(xa[j].z, h2, l2); split_bf16(xa[j].w, h3, l3);
                hh[2 * j]     = pack_bf16x2(h0, h1_); hh[2 * j + 1] = pack_bf16x2(h2, h3);
                ll[2 * j]     = pack_bf16x2(l0, l1);  ll[2 * j + 1] = pack_bf16x2(l2, l3);
            }
            *(uint4*)(sAh + sts)      = make_uint4(hh[0], hh[1], hh[2], hh[3]);
            *(uint4*)(sAh + sts + 16) = make_uint4(hh[4], hh[5], hh[6], hh[7]);
            *(uint4*)(sAl + sts)      = make_uint4(ll[0], ll[1], ll[2], ll[3]);
            *(uint4*)(sAl + sts + 16) = make_uint4(ll[4], ll[5], ll[6], ll[7]);
        }
        *(uint4*)(sBh + sts)      = wbh[0];
        *(uint4*)(sBh + sts + 16) = wbh[1];
        *(uint4*)(sBl + sts)      = wbl[0];
        *(uint4*)(sBl + sts + 16) = wbl[1];
        __syncthreads();

        // prefetch next tile (overlaps with ldmatrix/mma below)
        if (i < IN_DIM / 32 - 1) {
            const int off = (i + 1) * 32;
            if (doA) {
                #pragma unroll
                for (int j = 0; j < 4; j++) xa[j] = *(const float4*)(xp + off + j * 4);
            }
            wbh[0] = *(const uint4*)(wph + off); wbh[1] = *(const uint4*)(wph + off + 8);
            wbl[0] = *(const uint4*)(wpl + off); wbl[1] = *(const uint4*)(wpl + off + 8);
        }

        #pragma unroll
        for (int ks = 0; ks < 2; ks++) {
            uint32_t ah[4][4], al[4][4], bh[4][2], bl[4][2];
            const uint32_t akb = (uint32_t)(ks * 32 + (lane >> 4) * 16 + (lane & 15) * SROW);
            #pragma unroll
            for (int im = 0; im < 4; im++) {
                if (im < nim) {
                    const uint32_t mo = (uint32_t)(((it0 + im) * 16) * SROW) + akb;
                    ldsm_x4(ah[im], uAh + mo);
                    ldsm_x4(al[im], uAl + mo);
                }
            }
            const uint32_t bkb = (uint32_t)(ks * 32 + ((lane >> 3) & 1) * 16 + (lane & 7) * SROW);
            #pragma unroll
            for (int in = 0; in < 4; in++) {
                const uint32_t no = (uint32_t)((wn * 32 + in * 8) * SROW) + bkb;
                ldsm_x2(bh[in], uBh + no);
                ldsm_x2(bl[in], uBl + no);
            }
            #pragma unroll
            for (int im = 0; im < 4; im++) {
                if (im < nim) {
                    #pragma unroll
                    for (int in = 0; in < 4; in++) {
                        mma16816(acc[im][in], ah[im], bh[in]);
                        mma16816(acc[im][in], ah[im], bl[in]);
                        mma16816(acc[im][in], al[im], bh[in]);
                    }
                }
            }
        }
        __syncthreads();
    }

    // epilogue: bias + relu -> g_h1 (guard rows for last CTA)
    #pragma unroll
    for (int im = 0; im < 4; im++) {
        if (im < nim) {
            const int rowa = row0 + (it0 + im) * 16 + (lane >> 2);
            #pragma unroll
            for (int in = 0; in < 4; in++) {
                const int col = wn * 32 + in * 8 + 2 * (lane & 3);
                const float bb0 = b1[col], bb1 = b1[col + 1];
                float2 v0 = make_float2(fmaxf(acc[im][in][0] + bb0, 0.f),
                                        fmaxf(acc[im][in][1] + bb1, 0.f));
                float2 v1 = make_float2(fmaxf(acc[im][in][2] + bb0, 0.f),
                                        fmaxf(acc[im][in][3] + bb1, 0.f));
                if (rowa < BDIM)
                    *(float2*)&g_h1[(size_t)rowa * H1D + col] = v0;
                if (rowa + 8 < BDIM)
                    *(float2*)&g_h1[(size_t)(rowa + 8) * H1D + col] = v1;
            }
        }
    }
}

// ---------------------------------------------------------------------------
// Head v3: j-across-lanes layout (R5, unchanged).
// ---------------------------------------------------------------------------
__global__ __launch_bounds__(256) void k_head(const float* __restrict__ W2,
                                              const float* __restrict__ b2,
                                              const float* __restrict__ W3,
                                              const float* __restrict__ b3,
                                              const float* __restrict__ qparams)
{
    __shared__ float h1s[64][132];
    __shared__ float h2s[64][68];

    const int row0 = blockIdx.x * 64;
    const int tid  = threadIdx.x;

    #pragma unroll
    for (int i = 0; i < 8; i++) {
        const int f = tid + 256 * i;
        const int r = f >> 5, c4 = (f & 31) << 2;
        *(float4*)&h1s[r][c4] = *(const float4*)&g_h1[(size_t)(row0 + r) * H1D + c4];
    }
    __syncthreads();

    {
        const int j  = tid & 63;
        const int rg = tid >> 6;
        float acc[16];
        const float bj = b2[j];
        #pragma unroll
        for (int t = 0; t < 16; t++) acc[t] = bj;

        #pragma unroll 4
        for (int k = 0; k < H1D; k++) {
            const float w = W2[k * H2D + j];
            #pragma unroll
            for (int t = 0; t < 16; t++)
                acc[t] = fmaf(h1s[rg * 16 + t][k], w, acc[t]);
        }
        #pragma unroll
        for (int t = 0; t < 16; t++)
            h2s[rg * 16 + t][j] = fmaxf(acc[t], 0.f);
    }
    __syncthreads();

    {
        const int j2  = tid & 31;
        const int rg2 = tid >> 5;
        float base = b3[j2];
        #pragma unroll
        for (int rep = 0; rep < 2 * NREPS; rep++)
            base += qparams[rep * LAT + j2];

        float z[8];
        #pragma unroll
        for (int t = 0; t < 8; t++) z[t] = base;

        #pragma unroll 4
        for (int k = 0; k < H2D; k++) {
            const float w = W3[k * LAT + j2];
            #pragma unroll
            for (int t = 0; t < 8; t++)
                z[t] = fmaf(h2s[rg2 * 8 + t][k], w, z[t]);
        }

        #pragma unroll
        for (int t = 0; t < 8; t++) {
            const int row = row0 + rg2 * 8 + t;
            const float qv = cosf(z[t]);
            __nv_bfloat16 hh, ll;
            split_bf16(qv, hh, ll);
            g_q_h[(size_t)row * LAT + j2] = hh;
            g_q_l[(size_t)row * LAT + j2] = ll;
        }
    }
}

// ---------------------------------------------------------------------------
// GEMM2 (mma.sync): out = q @ Wd + bd.  CTA tile 128x128, K=32 single shot.
// (exact R5 version)
// ---------------------------------------------------------------------------
__global__ __launch_bounds__(256) void k_gemm2_mma(const float* __restrict__ bd,
                                                   float* __restrict__ out)
{
    __shared__ __align__(128) char sm[4 * 128 * SROW];
    char* sQh = sm;
    char* sQl = sm + 128 * SROW;
    char* sWh = sm + 2 * 128 * SROW;
    char* sWl = sm + 3 * 128 * SROW;
    const uint32_t uQh = smem_u32(sQh), uQl = smem_u32(sQl);
    const uint32_t uWh = smem_u32(sWh), uWl = smem_u32(sWl);

    const int tid  = threadIdx.x;
    const int lane = tid & 31, wid = tid >> 5;
    const int wm = wid >> 2, wn = wid & 3;
    const int r = tid >> 1, h = tid & 1;
    const int n0 = blockIdx.x * 128;
    const int m0 = blockIdx.y * 128;

    const uint32_t sts = (uint32_t)(r * SROW + h * 32);
    {
        const __nv_bfloat16* qh = &g_q_h[(size_t)(m0 + r) * LAT + h * 16];
        const __nv_bfloat16* ql = &g_q_l[(size_t)(m0 + r) * LAT + h * 16];
        const __nv_bfloat16* wh = &g_Wdt_h[(size_t)(n0 + r) * LAT + h * 16];
        const __nv_bfloat16* wl = &g_Wdt_l[(size_t)(n0 + r) * LAT + h * 16];
        *(uint4*)(sQh + sts)      = *(const uint4*)qh;
        *(uint4*)(sQh + sts + 16) = *(const uint4*)(qh + 8);
        *(uint4*)(sQl + sts)      = *(const uint4*)ql;
        *(uint4*)(sQl + sts + 16) = *(const uint4*)(ql + 8);
        *(uint4*)(sWh + sts)      = *(const uint4*)wh;
        *(uint4*)(sWh + sts + 16) = *(const uint4*)(wh + 8);
        *(uint4*)(sWl + sts)      = *(const uint4*)wl;
        *(uint4*)(sWl + sts + 16) = *(const uint4*)(wl + 8);
    }
    __syncthreads();

    float acc[4][4][4];
    #pragma unroll
    for (int im = 0; im < 4; im++)
        #pragma unroll
        for (int in = 0; in < 4; in++)
            #pragma unroll
            for (int j = 0; j < 4; j++) acc[im][in][j] = 0.f;

    #pragma unroll
    for (int ks = 0; ks < 2; ks++) {
        uint32_t ah[4][4], al[4][4], bh[4][2], bl[4][2];
        const uint32_t akb = (uint32_t)(ks * 32 + (lane >> 4) * 16 + (lane & 15) * SROW);
        #pragma unroll
        for (int im = 0; im < 4; im++) {
            const uint32_t mo = (uint32_t)((wm * 64 + im * 16) * SROW) + akb;
            ldsm_x4(ah[im], uQh + mo);
            ldsm_x4(al[im], uQl + mo);
        }
        const uint32_t bkb = (uint32_t)(ks * 32 + ((lane >> 3) & 1) * 16 + (lane & 7) * SROW);
        #pragma unroll
        for (int in = 0; in < 4; in++) {
            const uint32_t no = (uint32_t)((wn * 32 + in * 8) * SROW) + bkb;
            ldsm_x2(bh[in], uWh + no);
            ldsm_x2(bl[in], uWl + no);
        }
        #pragma unroll
        for (int im = 0; im < 4; im++)
            #pragma unroll
            for (int in = 0; in < 4; in++) {
                mma16816(acc[im][in], ah[im], bh[in]);
                mma16816(acc[im][in], ah[im], bl[in]);
                mma16816(acc[im][in], al[im], bh[in]);
            }
    }

    // epilogue: + bd -> out
    #pragma unroll
    for (int im = 0; im < 4; im++) {
        const int rowa = m0 + wm * 64 + im * 16 + (lane >> 2);
        #pragma unroll
        for (int in = 0; in < 4; in++) {
            const int col = n0 + wn * 32 + in * 8 + 2 * (lane & 3);
            const float bb0 = bd[col], bb1 = bd[col + 1];
            float2 v0 = make_float2(acc[im][in][0] + bb0, acc[im][in][1] + bb1);
            float2 v1 = make_float2(acc[im][in][2] + bb0, acc[im][in][3] + bb1);
            *(float2*)&out[(size_t)rowa * IN_DIM + col]       = v0;
            *(float2*)&out[(size_t)(rowa + 8) * IN_DIM + col] = v1;
        }
    }
}

// ---------------------------------------------------------------------------
extern "C" void kernel_launch(void* const* d_in, const int* in_sizes, int n_in,
                              void* d_out, int out_size)
{
    const float* x  = (const float*)d_in[0];
    const float* W1 = (const float*)d_in[1];
    const float* b1 = (const float*)d_in[2];
    const float* W2 = (const float*)d_in[3];
    const float* b2 = (const float*)d_in[4];
    const float* W3 = (const float*)d_in[5];
    const float* b3 = (const float*)d_in[6];
    const float* qp = (const float*)d_in[7];
    const float* Wd = (const float*)d_in[8];
    const float* bd = (const float*)d_in[9];
    float* out = (float*)d_out;

    k_prep<<<dim3(IN_DIM / 32, 5), dim3(32, 8)>>>(W1, Wd);
    k_gemm1_mma<<<(BDIM + MTILE - 1) / MTILE, 256>>>(x, b1);     // 147 CTAs, 1 wave
    k_head<<<BDIM / 64, 256>>>(W2, b2, W3, b3, qp);
    k_gemm2_mma<<<dim3(IN_DIM / 128, BDIM / 128), 256>>>(bd, out);
}

// round 14
// speedup vs baseline: 1.0879x; 1.0879x over previous
#include <cuda_runtime.h>
#include <cuda_bf16.h>
#include <cstdint>
#include <math.h>

#define BDIM   16384
#define IN_DIM 4096
#define H1D    128
#define H2D    64
#define LAT    32
#define NREPS  3
#define SROW   80        // padded smem row stride (bytes) for 32 bf16 = 64B data

// ---------------------------------------------------------------------------
// Scratch (__device__ globals: allocation-free rule)
// ---------------------------------------------------------------------------
__device__ float g_h1[(size_t)BDIM * H1D];                            // 8 MB
__device__ __align__(16) __nv_bfloat16 g_q_h[(size_t)BDIM * LAT];
__device__ __align__(16) __nv_bfloat16 g_q_l[(size_t)BDIM * LAT];
__device__ __align__(16) __nv_bfloat16 g_W1t_h[(size_t)H1D * IN_DIM]; // W1^T [n][k]
__device__ __align__(16) __nv_bfloat16 g_W1t_l[(size_t)H1D * IN_DIM];
__device__ __align__(16) __nv_bfloat16 g_Wdt_h[(size_t)IN_DIM * LAT]; // Wd^T [n][k]
__device__ __align__(16) __nv_bfloat16 g_Wdt_l[(size_t)IN_DIM * LAT];

// ---------------------------------------------------------------------------
// Helpers (baseline PTX only: ldmatrix + mma.sync, sm_80-compatible)
// ---------------------------------------------------------------------------
__device__ __forceinline__ uint32_t smem_u32(const void* p) {
    uint32_t a;
    asm("{ .reg .u64 t; cvta.to.shared.u64 t, %1; cvt.u32.u64 %0, t; }" : "=r"(a) : "l"(p));
    return a;
}
__device__ __forceinline__ void ldsm_x4(uint32_t* r, uint32_t addr) {
    asm volatile("ldmatrix.sync.aligned.m8n8.x4.shared.b16 {%0,%1,%2,%3}, [%4];"
                 : "=r"(r[0]), "=r"(r[1]), "=r"(r[2]), "=r"(r[3]) : "r"(addr));
}
__device__ __forceinline__ void ldsm_x2(uint32_t* r, uint32_t addr) {
    asm volatile("ldmatrix.sync.aligned.m8n8.x2.shared.b16 {%0,%1}, [%2];"
                 : "=r"(r[0]), "=r"(r[1]) : "r"(addr));
}
__device__ __forceinline__ void mma16816(float* c, const uint32_t* a, const uint32_t* b) {
    asm volatile("mma.sync.aligned.m16n8k16.row.col.f32.bf16.bf16.f32 "
                 "{%0,%1,%2,%3}, {%4,%5,%6,%7}, {%8,%9}, {%0,%1,%2,%3};"
                 : "+f"(c[0]), "+f"(c[1]), "+f"(c[2]), "+f"(c[3])
                 : "r"(a[0]), "r"(a[1]), "r"(a[2]), "r"(a[3]), "r"(b[0]), "r"(b[1]));
}
__device__ __forceinline__ uint32_t pack_bf16x2(__nv_bfloat16 a, __nv_bfloat16 b) {
    return (uint32_t)__bfloat16_as_ushort(a) | ((uint32_t)__bfloat16_as_ushort(b) << 16);
}
__device__ __forceinline__ void split_bf16(float v, __nv_bfloat16& hi, __nv_bfloat16& lo) {
    hi = __float2bfloat16_rn(v);
    lo = __float2bfloat16_rn(v - __bfloat162float(hi));
}

// ---------------------------------------------------------------------------
// Merged prep: y<4 -> W1 transpose+split tiles; y==4 -> Wd transpose+split.
// ---------------------------------------------------------------------------
__global__ void k_prep(const float* __restrict__ W1, const float* __restrict__ Wd) {
    __shared__ float t[32][33];
    const int tx = threadIdx.x, ty = threadIdx.y;   // (32, 8)
    if (blockIdx.y < 4) {
        const int k0 = blockIdx.x * 32, n0 = blockIdx.y * 32;
        #pragma unroll
        for (int i = 0; i < 4; i++)
            t[ty + 8 * i][tx] = W1[(size_t)(k0 + ty + 8 * i) * H1D + n0 + tx];
        __syncthreads();
        #pragma unroll
        for (int i = 0; i < 4; i++) {
            const int n = n0 + ty + 8 * i, k = k0 + tx;
            __nv_bfloat16 h, l;
            split_bf16(t[tx][ty + 8 * i], h, l);
            g_W1t_h[(size_t)n * IN_DIM + k] = h;
            g_W1t_l[(size_t)n * IN_DIM + k] = l;
        }
    } else {
        const int n0 = blockIdx.x * 32;
        #pragma unroll
        for (int i = 0; i < 4; i++)
            t[ty + 8 * i][tx] = Wd[(size_t)(ty + 8 * i) * IN_DIM + n0 + tx];
        __syncthreads();
        #pragma unroll
        for (int i = 0; i < 4; i++) {
            const int n = n0 + ty + 8 * i, k = tx;
            __nv_bfloat16 h, l;
            split_bf16(t[tx][ty + 8 * i], h, l);
            g_Wdt_h[(size_t)n * LAT + k] = h;
            g_Wdt_l[(size_t)n * LAT + k] = l;
        }
    }
}

// ---------------------------------------------------------------------------
// GEMM1 (mma.sync): h1 = relu(x @ W1 + b1)   [exact R5 version, 281us config]
// CTA tile 128x128, BK=32, 8 warps (2x4), warp tile 64x32.
// ---------------------------------------------------------------------------
__global__ __launch_bounds__(256) void k_gemm1_mma(const float* __restrict__ x,
                                                   const float* __restrict__ b1)
{
    __shared__ __align__(128) char sm[4 * 128 * SROW];   // Ah, Al, Bh, Bl (40 KB)
    char* sAh = sm;
    char* sAl = sm + 128 * SROW;
    char* sBh = sm + 2 * 128 * SROW;
    char* sBl = sm + 3 * 128 * SROW;
    const uint32_t uAh = smem_u32(sAh), uAl = smem_u32(sAl);
    const uint32_t uBh = smem_u32(sBh), uBl = smem_u32(sBl);

    const int tid  = threadIdx.x;
    const int lane = tid & 31, wid = tid >> 5;
    const int wm = wid >> 2, wn = wid & 3;         // warp grid 2(m) x 4(n)
    const int r = tid >> 1, h = tid & 1;           // load role: row, k-half
    const int row0 = blockIdx.x * 128;

    float acc[4][4][4];
    #pragma unroll
    for (int im = 0; im < 4; im++)
        #pragma unroll
        for (int in = 0; in < 4; in++)
            #pragma unroll
            for (int j = 0; j < 4; j++) acc[im][in][j] = 0.f;

    const float*         xp  = &x[(size_t)(row0 + r) * IN_DIM + h * 16];
    const __nv_bfloat16* wph = &g_W1t_h[(size_t)r * IN_DIM + h * 16];
    const __nv_bfloat16* wpl = &g_W1t_l[(size_t)r * IN_DIM + h * 16];

    // prefetch iter 0
    float4 xa[4]; uint4 wbh[2], wbl[2];
    #pragma unroll
    for (int j = 0; j < 4; j++) xa[j] = *(const float4*)(xp + j * 4);
    wbh[0] = *(const uint4*)wph; wbh[1] = *(const uint4*)(wph + 8);
    wbl[0] = *(const uint4*)wpl; wbl[1] = *(const uint4*)(wpl + 8);

    const uint32_t sts = (uint32_t)(r * SROW + h * 32);

    for (int i = 0; i < IN_DIM / 32; ++i) {
        // convert + STS of current tile
        uint32_t hh[8], ll[8];
        #pragma unroll
        for (int j = 0; j < 4; j++) {
            __nv_bfloat16 h0, l0, h1_, l1, h2, l2, h3, l3;
            split_bf16(xa[j].x, h0, l0); split_bf16(xa[j].y, h1_, l1);
            split_bf16(xa[j].z, h2, l2); split_bf16(xa[j].w, h3, l3);
            hh[2 * j]     = pack_bf16x2(h0, h1_); hh[2 * j + 1] = pack_bf16x2(h2, h3);
            ll[2 * j]     = pack_bf16x2(l0, l1);  ll[2 * j + 1] = pack_bf16x2(l2, l3);
        }
        *(uint4*)(sAh + sts)      = make_uint4(hh[0], hh[1], hh[2], hh[3]);
        *(uint4*)(sAh + sts + 16) = make_uint4(hh[4], hh[5], hh[6], hh[7]);
        *(uint4*)(sAl + sts)      = make_uint4(ll[0], ll[1], ll[2], ll[3]);
        *(uint4*)(sAl + sts + 16) = make_uint4(ll[4], ll[5], ll[6], ll[7]);
        *(uint4*)(sBh + sts)      = wbh[0];
        *(uint4*)(sBh + sts + 16) = wbh[1];
        *(uint4*)(sBl + sts)      = wbl[0];
        *(uint4*)(sBl + sts + 16) = wbl[1];
        __syncthreads();

        // prefetch next tile (overlaps with ldmatrix/mma below)
        if (i < IN_DIM / 32 - 1) {
            const int off = (i + 1) * 32;
            #pragma unroll
            for (int j = 0; j < 4; j++) xa[j] = *(const float4*)(xp + off + j * 4);
            wbh[0] = *(const uint4*)(wph + off); wbh[1] = *(const uint4*)(wph + off + 8);
            wbl[0] = *(const uint4*)(wpl + off); wbl[1] = *(const uint4*)(wpl + off + 8);
        }

        #pragma unroll
        for (int ks = 0; ks < 2; ks++) {
            uint32_t ah[4][4], al[4][4], bh[4][2], bl[4][2];
            const uint32_t akb = (uint32_t)(ks * 32 + (lane >> 4) * 16 + (lane & 15) * SROW);
            #pragma unroll
            for (int im = 0; im < 4; im++) {
                const uint32_t mo = (uint32_t)((wm * 64 + im * 16) * SROW) + akb;
                ldsm_x4(ah[im], uAh + mo);
                ldsm_x4(al[im], uAl + mo);
            }
            const uint32_t bkb = (uint32_t)(ks * 32 + ((lane >> 3) & 1) * 16 + (lane & 7) * SROW);
            #pragma unroll
            for (int in = 0; in < 4; in++) {
                const uint32_t no = (uint32_t)((wn * 32 + in * 8) * SROW) + bkb;
                ldsm_x2(bh[in], uBh + no);
                ldsm_x2(bl[in], uBl + no);
            }
            #pragma unroll
            for (int im = 0; im < 4; im++)
                #pragma unroll
                for (int in = 0; in < 4; in++) {
                    mma16816(acc[im][in], ah[im], bh[in]);
                    mma16816(acc[im][in], ah[im], bl[in]);
                    mma16816(acc[im][in], al[im], bh[in]);
                }
        }
        __syncthreads();
    }

    // epilogue: bias + relu -> g_h1
    #pragma unroll
    for (int im = 0; im < 4; im++) {
        const int rowa = row0 + wm * 64 + im * 16 + (lane >> 2);
        #pragma unroll
        for (int in = 0; in < 4; in++) {
            const int col = wn * 32 + in * 8 + 2 * (lane & 3);
            const float bb0 = b1[col], bb1 = b1[col + 1];
            float2 v0 = make_float2(fmaxf(acc[im][in][0] + bb0, 0.f),
                                    fmaxf(acc[im][in][1] + bb1, 0.f));
            float2 v1 = make_float2(fmaxf(acc[im][in][2] + bb0, 0.f),
                                    fmaxf(acc[im][in][3] + bb1, 0.f));
            *(float2*)&g_h1[(size_t)rowa * H1D + col]       = v0;
            *(float2*)&g_h1[(size_t)(rowa + 8) * H1D + col] = v1;
        }
    }
}

// ---------------------------------------------------------------------------
// Head v3: j-across-lanes layout (R5, unchanged).
// ---------------------------------------------------------------------------
__global__ __launch_bounds__(256) void k_head(const float* __restrict__ W2,
                                              const float* __restrict__ b2,
                                              const float* __restrict__ W3,
                                              const float* __restrict__ b3,
                                              const float* __restrict__ qparams)
{
    __shared__ float h1s[64][132];
    __shared__ float h2s[64][68];

    const int row0 = blockIdx.x * 64;
    const int tid  = threadIdx.x;

    #pragma unroll
    for (int i = 0; i < 8; i++) {
        const int f = tid + 256 * i;
        const int r = f >> 5, c4 = (f & 31) << 2;
        *(float4*)&h1s[r][c4] = *(const float4*)&g_h1[(size_t)(row0 + r) * H1D + c4];
    }
    __syncthreads();

    {
        const int j  = tid & 63;
        const int rg = tid >> 6;
        float acc[16];
        const float bj = b2[j];
        #pragma unroll
        for (int t = 0; t < 16; t++) acc[t] = bj;

        #pragma unroll 4
        for (int k = 0; k < H1D; k++) {
            const float w = W2[k * H2D + j];
            #pragma unroll
            for (int t = 0; t < 16; t++)
                acc[t] = fmaf(h1s[rg * 16 + t][k], w, acc[t]);
        }
        #pragma unroll
        for (int t = 0; t < 16; t++)
            h2s[rg * 16 + t][j] = fmaxf(acc[t], 0.f);
    }
    __syncthreads();

    {
        const int j2  = tid & 31;
        const int rg2 = tid >> 5;
        float base = b3[j2];
        #pragma unroll
        for (int rep = 0; rep < 2 * NREPS; rep++)
            base += qparams[rep * LAT + j2];

        float z[8];
        #pragma unroll
        for (int t = 0; t < 8; t++) z[t] = base;

        #pragma unroll 4
        for (int k = 0; k < H2D; k++) {
            const float w = W3[k * LAT + j2];
            #pragma unroll
            for (int t = 0; t < 8; t++)
                z[t] = fmaf(h2s[rg2 * 8 + t][k], w, z[t]);
        }

        #pragma unroll
        for (int t = 0; t < 8; t++) {
            const int row = row0 + rg2 * 8 + t;
            const float qv = cosf(z[t]);
            __nv_bfloat16 hh, ll;
            split_bf16(qv, hh, ll);
            g_q_h[(size_t)row * LAT + j2] = hh;
            g_q_l[(size_t)row * LAT + j2] = ll;
        }
    }
}

// ---------------------------------------------------------------------------
// GEMM2 v3 (mma.sync): out = q @ Wd + bd.  CTA tile 128x128, K=32.
// SMEM-FREE: MMA fragments are 4B-aligned contiguous pairs in the natural
// [row][k] layouts of g_q_* / g_Wdt_*, so they are LDG'd straight into regs.
// No STS, no ldmatrix, no __syncthreads.  Fragment words are bit-identical
// to the R5 ldsm path.
// ---------------------------------------------------------------------------
__global__ __launch_bounds__(256) void k_gemm2_mma(const float* __restrict__ bd,
                                                   float* __restrict__ out)
{
    const int tid  = threadIdx.x;
    const int lane = tid & 31, wid = tid >> 5;
    const int wm = wid >> 2, wn = wid & 3;
    const int n0 = blockIdx.x * 128;
    const int m0 = blockIdx.y * 128;

    const int lg = lane >> 2;          // fragment row group 0..7
    const int lk = 2 * (lane & 3);     // fragment k offset 0,2,4,6

    float acc[4][4][4];
    #pragma unroll
    for (int im = 0; im < 4; im++)
        #pragma unroll
        for (int in = 0; in < 4; in++)
            #pragma unroll
            for (int j = 0; j < 4; j++) acc[im][in][j] = 0.f;

    // base element offsets (row * 32 + k) for this lane
    const int arow = m0 + wm * 64 + lg;            // + im*16 (+8 for odd reg)
    const int brow = n0 + wn * 32 + lg;            // + in*8

    #pragma unroll
    for (int ks = 0; ks < 2; ks++) {
        const int kb = ks * 16 + lk;               // + 8 for hi-k regs

        uint32_t ah[4][4], al[4][4], bh[4][2], bl[4][2];
        #pragma unroll
        for (int im = 0; im < 4; im++) {
            const size_t r0 = (size_t)(arow + im * 16) * LAT + kb;
            const size_t r1 = (size_t)(arow + im * 16 + 8) * LAT + kb;
            ah[im][0] = *(const uint32_t*)&g_q_h[r0];
            ah[im][1] = *(const uint32_t*)&g_q_h[r1];
            ah[im][2] = *(const uint32_t*)&g_q_h[r0 + 8];
            ah[im][3] = *(const uint32_t*)&g_q_h[r1 + 8];
            al[im][0] = *(const uint32_t*)&g_q_l[r0];
            al[im][1] = *(const uint32_t*)&g_q_l[r1];
            al[im][2] = *(const uint32_t*)&g_q_l[r0 + 8];
            al[im][3] = *(const uint32_t*)&g_q_l[r1 + 8];
        }
        #pragma unroll
        for (int in = 0; in < 4; in++) {
            const size_t r0 = (size_t)(brow + in * 8) * LAT + kb;
            bh[in][0] = *(const uint32_t*)&g_Wdt_h[r0];
            bh[in][1] = *(const uint32_t*)&g_Wdt_h[r0 + 8];
            bl[in][0] = *(const uint32_t*)&g_Wdt_l[r0];
            bl[in][1] = *(const uint32_t*)&g_Wdt_l[r0 + 8];
        }

        #pragma unroll
        for (int im = 0; im < 4; im++)
            #pragma unroll
            for (int in = 0; in < 4; in++) {
                mma16816(acc[im][in], ah[im], bh[in]);
                mma16816(acc[im][in], ah[im], bl[in]);
                mma16816(acc[im][in], al[im], bh[in]);
            }
    }

    // epilogue: + bd -> out
    #pragma unroll
    for (int im = 0; im < 4; im++) {
        const int rowa = m0 + wm * 64 + im * 16 + lg;
        #pragma unroll
        for (int in = 0; in < 4; in++) {
            const int col = n0 + wn * 32 + in * 8 + lk;
            const float bb0 = bd[col], bb1 = bd[col + 1];
            float2 v0 = make_float2(acc[im][in][0] + bb0, acc[im][in][1] + bb1);
            float2 v1 = make_float2(acc[im][in][2] + bb0, acc[im][in][3] + bb1);
            *(float2*)&out[(size_t)rowa * IN_DIM + col]       = v0;
            *(float2*)&out[(size_t)(rowa + 8) * IN_DIM + col] = v1;
        }
    }
}

// ---------------------------------------------------------------------------
extern "C" void kernel_launch(void* const* d_in, const int* in_sizes, int n_in,
                              void* d_out, int out_size)
{
    const float* x  = (const float*)d_in[0];
    const float* W1 = (const float*)d_in[1];
    const float* b1 = (const float*)d_in[2];
    const float* W2 = (const float*)d_in[3];
    const float* b2 = (const float*)d_in[4];
    const float* W3 = (const float*)d_in[5];
    const float* b3 = (const float*)d_in[6];
    const float* qp = (const float*)d_in[7];
    const float* Wd = (const float*)d_in[8];
    const float* bd = (const float*)d_in[9];
    float* out = (float*)d_out;

    k_prep<<<dim3(IN_DIM / 32, 5), dim3(32, 8)>>>(W1, Wd);
    k_gemm1_mma<<<BDIM / 128, 256>>>(x, b1);
    k_head<<<BDIM / 64, 256>>>(W2, b2, W3, b3, qp);
    k_gemm2_mma<<<dim3(IN_DIM / 128, BDIM / 128), 256>>>(bd, out);
}

// round 15
// speedup vs baseline: 1.0970x; 1.0084x over previous
#include <cuda_runtime.h>
#include <cuda_bf16.h>
#include <cstdint>
#include <math.h>

#define BDIM   16384
#define IN_DIM 4096
#define H1D    128
#define H2D    64
#define LAT    32
#define NREPS  3
#define SROW   80        // padded smem row stride (bytes) for 32 bf16 = 64B data

// ---------------------------------------------------------------------------
// Scratch (__device__ globals: allocation-free rule)
// ---------------------------------------------------------------------------
__device__ float g_h1[(size_t)BDIM * H1D];                            // 8 MB
__device__ __align__(16) __nv_bfloat16 g_W1t_h[(size_t)H1D * IN_DIM]; // W1^T [n][k]
__device__ __align__(16) __nv_bfloat16 g_W1t_l[(size_t)H1D * IN_DIM];
// q packed as mma A-fragments: [rowtile(1024)][ks(2)][lane(32)][reg(4)]
__device__ __align__(16) uint32_t g_qf_h[(BDIM / 16) * 2 * 32 * 4];   // 1 MB
__device__ __align__(16) uint32_t g_qf_l[(BDIM / 16) * 2 * 32 * 4];
// Wd packed as mma B-fragments: [ntile(512)][ks(2)][lane(32)][reg(2)]
__device__ __align__(16) uint32_t g_Wdf_h[(IN_DIM / 8) * 2 * 32 * 2]; // 256 KB
__device__ __align__(16) uint32_t g_Wdf_l[(IN_DIM / 8) * 2 * 32 * 2];

// ---------------------------------------------------------------------------
// Helpers (baseline PTX only: ldmatrix + mma.sync, sm_80-compatible)
// ---------------------------------------------------------------------------
__device__ __forceinline__ uint32_t smem_u32(const void* p) {
    uint32_t a;
    asm("{ .reg .u64 t; cvta.to.shared.u64 t, %1; cvt.u32.u64 %0, t; }" : "=r"(a) : "l"(p));
    return a;
}
__device__ __forceinline__ void ldsm_x4(uint32_t* r, uint32_t addr) {
    asm volatile("ldmatrix.sync.aligned.m8n8.x4.shared.b16 {%0,%1,%2,%3}, [%4];"
                 : "=r"(r[0]), "=r"(r[1]), "=r"(r[2]), "=r"(r[3]) : "r"(addr));
}
__device__ __forceinline__ void ldsm_x2(uint32_t* r, uint32_t addr) {
    asm volatile("ldmatrix.sync.aligned.m8n8.x2.shared.b16 {%0,%1}, [%2];"
                 : "=r"(r[0]), "=r"(r[1]) : "r"(addr));
}
__device__ __forceinline__ void mma16816(float* c, const uint32_t* a, const uint32_t* b) {
    asm volatile("mma.sync.aligned.m16n8k16.row.col.f32.bf16.bf16.f32 "
                 "{%0,%1,%2,%3}, {%4,%5,%6,%7}, {%8,%9}, {%0,%1,%2,%3};"
                 : "+f"(c[0]), "+f"(c[1]), "+f"(c[2]), "+f"(c[3])
                 : "r"(a[0]), "r"(a[1]), "r"(a[2]), "r"(a[3]), "r"(b[0]), "r"(b[1]));
}
__device__ __forceinline__ uint32_t pack_bf16x2(__nv_bfloat16 a, __nv_bfloat16 b) {
    return (uint32_t)__bfloat16_as_ushort(a) | ((uint32_t)__bfloat16_as_ushort(b) << 16);
}
__device__ __forceinline__ void split_bf16(float v, __nv_bfloat16& hi, __nv_bfloat16& lo) {
    hi = __float2bfloat16_rn(v);
    lo = __float2bfloat16_rn(v - __bfloat162float(hi));
}

// ---------------------------------------------------------------------------
// Merged prep: y<4 -> W1 transpose+split tiles; y==4 -> Wd fragment packing.
// B-fragment word (n, kp): lane=(n&7)*4+(kp&3), reg=(kp&7)>>2, ks=kp>>3,
// ntile=n>>3; idx = ((ntile*2+ks)*32+lane)*2 + reg.
// ---------------------------------------------------------------------------
__global__ void k_prep(const float* __restrict__ W1, const float* __restrict__ Wd) {
    __shared__ float t[32][33];
    const int tx = threadIdx.x, ty = threadIdx.y;   // (32, 8)
    if (blockIdx.y < 4) {
        const int k0 = blockIdx.x * 32, n0 = blockIdx.y * 32;
        #pragma unroll
        for (int i = 0; i < 4; i++)
            t[ty + 8 * i][tx] = W1[(size_t)(k0 + ty + 8 * i) * H1D + n0 + tx];
        __syncthreads();
        #pragma unroll
        for (int i = 0; i < 4; i++) {
            const int n = n0 + ty + 8 * i, k = k0 + tx;
            __nv_bfloat16 h, l;
            split_bf16(t[tx][ty + 8 * i], h, l);
            g_W1t_h[(size_t)n * IN_DIM + k] = h;
            g_W1t_l[(size_t)n * IN_DIM + k] = l;
        }
    } else {
        const int n0 = blockIdx.x * 32;
        #pragma unroll
        for (int i = 0; i < 4; i++)
            t[ty + 8 * i][tx] = Wd[(size_t)(ty + 8 * i) * IN_DIM + n0 + tx];   // t[k][nl]
        __syncthreads();
        const int kp = tx & 15, half = tx >> 4;
        #pragma unroll
        for (int i = 0; i < 4; i++) {
            const int nl = ty + 8 * i, n = n0 + nl;
            __nv_bfloat16 h0, l0, h1, l1;
            split_bf16(t[2 * kp][nl], h0, l0);
            split_bf16(t[2 * kp + 1][nl], h1, l1);
            const uint32_t word = half ? pack_bf16x2(l0, l1) : pack_bf16x2(h0, h1);
            const int ntile = n >> 3, ks = kp >> 3;
            const int lane = (n & 7) * 4 + (kp & 3);
            const int reg  = (kp & 7) >> 2;
            const int idx  = ((ntile * 2 + ks) * 32 + lane) * 2 + reg;
            if (half) g_Wdf_l[idx] = word; else g_Wdf_h[idx] = word;
        }
    }
}

// ---------------------------------------------------------------------------
// GEMM1 (mma.sync): h1 = relu(x @ W1 + b1)   [exact R5 version, 281us config]
// CTA tile 128x128, BK=32, 8 warps (2x4), warp tile 64x32.
// ---------------------------------------------------------------------------
__global__ __launch_bounds__(256) void k_gemm1_mma(const float* __restrict__ x,
                                                   const float* __restrict__ b1)
{
    __shared__ __align__(128) char sm[4 * 128 * SROW];   // Ah, Al, Bh, Bl (40 KB)
    char* sAh = sm;
    char* sAl = sm + 128 * SROW;
    char* sBh = sm + 2 * 128 * SROW;
    char* sBl = sm + 3 * 128 * SROW;
    const uint32_t uAh = smem_u32(sAh), uAl = smem_u32(sAl);
    const uint32_t uBh = smem_u32(sBh), uBl = smem_u32(sBl);

    const int tid  = threadIdx.x;
    const int lane = tid & 31, wid = tid >> 5;
    const int wm = wid >> 2, wn = wid & 3;         // warp grid 2(m) x 4(n)
    const int r = tid >> 1, h = tid & 1;           // load role: row, k-half
    const int row0 = blockIdx.x * 128;

    float acc[4][4][4];
    #pragma unroll
    for (int im = 0; im < 4; im++)
        #pragma unroll
        for (int in = 0; in < 4; in++)
            #pragma unroll
            for (int j = 0; j < 4; j++) acc[im][in][j] = 0.f;

    const float*         xp  = &x[(size_t)(row0 + r) * IN_DIM + h * 16];
    const __nv_bfloat16* wph = &g_W1t_h[(size_t)r * IN_DIM + h * 16];
    const __nv_bfloat16* wpl = &g_W1t_l[(size_t)r * IN_DIM + h * 16];

    // prefetch iter 0
    float4 xa[4]; uint4 wbh[2], wbl[2];
    #pragma unroll
    for (int j = 0; j < 4; j++) xa[j] = *(const float4*)(xp + j * 4);
    wbh[0] = *(const uint4*)wph; wbh[1] = *(const uint4*)(wph + 8);
    wbl[0] = *(const uint4*)wpl; wbl[1] = *(const uint4*)(wpl + 8);

    const uint32_t sts = (uint32_t)(r * SROW + h * 32);

    for (int i = 0; i < IN_DIM / 32; ++i) {
        // convert + STS of current tile
        uint32_t hh[8], ll[8];
        #pragma unroll
        for (int j = 0; j < 4; j++) {
            __nv_bfloat16 h0, l0, h1_, l1, h2, l2, h3, l3;
            split_bf16(xa[j].x, h0, l0); split_bf16(xa[j].y, h1_, l1);
            split_bf16(xa[j].z, h2, l2); split_bf16(xa[j].w, h3, l3);
            hh[2 * j]     = pack_bf16x2(h0, h1_); hh[2 * j + 1] = pack_bf16x2(h2, h3);
            ll[2 * j]     = pack_bf16x2(l0, l1);  ll[2 * j + 1] = pack_bf16x2(l2, l3);
        }
        *(uint4*)(sAh + sts)      = make_uint4(hh[0], hh[1], hh[2], hh[3]);
        *(uint4*)(sAh + sts + 16) = make_uint4(hh[4], hh[5], hh[6], hh[7]);
        *(uint4*)(sAl + sts)      = make_uint4(ll[0], ll[1], ll[2], ll[3]);
        *(uint4*)(sAl + sts + 16) = make_uint4(ll[4], ll[5], ll[6], ll[7]);
        *(uint4*)(sBh + sts)      = wbh[0];
        *(uint4*)(sBh + sts + 16) = wbh[1];
        *(uint4*)(sBl + sts)      = wbl[0];
        *(uint4*)(sBl + sts + 16) = wbl[1];
        __syncthreads();

        // prefetch next tile (overlaps with ldmatrix/mma below)
        if (i < IN_DIM / 32 - 1) {
            const int off = (i + 1) * 32;
            #pragma unroll
            for (int j = 0; j < 4; j++) xa[j] = *(const float4*)(xp + off + j * 4);
            wbh[0] = *(const uint4*)(wph + off); wbh[1] = *(const uint4*)(wph + off + 8);
            wbl[0] = *(const uint4*)(wpl + off); wbl[1] = *(const uint4*)(wpl + off + 8);
        }

        #pragma unroll
        for (int ks = 0; ks < 2; ks++) {
            uint32_t ah[4][4], al[4][4], bh[4][2], bl[4][2];
            const uint32_t akb = (uint32_t)(ks * 32 + (lane >> 4) * 16 + (lane & 15) * SROW);
            #pragma unroll
            for (int im = 0; im < 4; im++) {
                const uint32_t mo = (uint32_t)((wm * 64 + im * 16) * SROW) + akb;
                ldsm_x4(ah[im], uAh + mo);
                ldsm_x4(al[im], uAl + mo);
            }
            const uint32_t bkb = (uint32_t)(ks * 32 + ((lane >> 3) & 1) * 16 + (lane & 7) * SROW);
            #pragma unroll
            for (int in = 0; in < 4; in++) {
                const uint32_t no = (uint32_t)((wn * 32 + in * 8) * SROW) + bkb;
                ldsm_x2(bh[in], uBh + no);
                ldsm_x2(bl[in], uBl + no);
            }
            #pragma unroll
            for (int im = 0; im < 4; im++)
                #pragma unroll
                for (int in = 0; in < 4; in++) {
                    mma16816(acc[im][in], ah[im], bh[in]);
                    mma16816(acc[im][in], ah[im], bl[in]);
                    mma16816(acc[im][in], al[im], bh[in]);
                }
        }
        __syncthreads();
    }

    // epilogue: bias + relu -> g_h1
    #pragma unroll
    for (int im = 0; im < 4; im++) {
        const int rowa = row0 + wm * 64 + im * 16 + (lane >> 2);
        #pragma unroll
        for (int in = 0; in < 4; in++) {
            const int col = wn * 32 + in * 8 + 2 * (lane & 3);
            const float bb0 = b1[col], bb1 = b1[col + 1];
            float2 v0 = make_float2(fmaxf(acc[im][in][0] + bb0, 0.f),
                                    fmaxf(acc[im][in][1] + bb1, 0.f));
            float2 v1 = make_float2(fmaxf(acc[im][in][2] + bb0, 0.f),
                                    fmaxf(acc[im][in][3] + bb1, 0.f));
            *(float2*)&g_h1[(size_t)rowa * H1D + col]       = v0;
            *(float2*)&g_h1[(size_t)(rowa + 8) * H1D + col] = v1;
        }
    }
}

// ---------------------------------------------------------------------------
// Head v5: stage 1 as R5; stage 2 re-mapped so each thread owns a column PAIR
// (2jp, 2jp+1) x 4 rows and emits q directly as packed A-fragment words.
// A-fragment word (row, kp): lane=(row&7)*4+(kp&3), reg=((row&15)>>3)+2*((kp&7)>>2),
// ks=kp>>3, rowtile=row>>4; idx = ((rowtile*2+ks)*32+lane)*4 + reg.
// ---------------------------------------------------------------------------
__global__ __launch_bounds__(256) void k_head(const float* __restrict__ W2,
                                              const float* __restrict__ b2,
                                              const float* __restrict__ W3,
                                              const float* __restrict__ b3,
                                              const float* __restrict__ qparams)
{
    __shared__ float h1s[64][132];
    __shared__ float h2s[64][68];

    const int row0 = blockIdx.x * 64;
    const int tid  = threadIdx.x;

    #pragma unroll
    for (int i = 0; i < 8; i++) {
        const int f = tid + 256 * i;
        const int r = f >> 5, c4 = (f & 31) << 2;
        *(float4*)&h1s[r][c4] = *(const float4*)&g_h1[(size_t)(row0 + r) * H1D + c4];
    }
    __syncthreads();

    {
        const int j  = tid & 63;
        const int rg = tid >> 6;
        float acc[16];
        const float bj = b2[j];
        #pragma unroll
        for (int t = 0; t < 16; t++) acc[t] = bj;

        #pragma unroll 4
        for (int k = 0; k < H1D; k++) {
            const float w = W2[k * H2D + j];
            #pragma unroll
            for (int t = 0; t < 16; t++)
                acc[t] = fmaf(h1s[rg * 16 + t][k], w, acc[t]);
        }
        #pragma unroll
        for (int t = 0; t < 16; t++)
            h2s[rg * 16 + t][j] = fmaxf(acc[t], 0.f);
    }
    __syncthreads();

    {
        const int jp = tid & 15;            // column pair: cols 2jp, 2jp+1
        const int rg = tid >> 4;            // 0..15 -> rows rg*4 .. +4
        float base0 = b3[2 * jp],     base1 = b3[2 * jp + 1];
        #pragma unroll
        for (int rep = 0; rep < 2 * NREPS; rep++) {
            base0 += qparams[rep * LAT + 2 * jp];
            base1 += qparams[rep * LAT + 2 * jp + 1];
        }

        float z0[4], z1[4];
        #pragma unroll
        for (int t = 0; t < 4; t++) { z0[t] = base0; z1[t] = base1; }

        #pragma unroll 4
        for (int k = 0; k < H2D; k++) {
            const float2 w = *(const float2*)&W3[k * LAT + 2 * jp];
            #pragma unroll
            for (int t = 0; t < 4; t++) {
                const float hv = h2s[rg * 4 + t][k];
                z0[t] = fmaf(hv, w.x, z0[t]);
                z1[t] = fmaf(hv, w.y, z1[t]);
            }
        }

        const int ks = jp >> 3;
        const int lane_kp = jp & 3;
        const int reg_kp  = 2 * ((jp & 7) >> 2);
        #pragma unroll
        for (int t = 0; t < 4; t++) {
            const int row = row0 + rg * 4 + t;
            const float q0 = cosf(z0[t]), q1 = cosf(z1[t]);
            __nv_bfloat16 h0, l0, h1, l1;
            split_bf16(q0, h0, l0);
            split_bf16(q1, h1, l1);
            const int rowtile = row >> 4, rl = row & 15;
            const int lane = (rl & 7) * 4 + lane_kp;
            const int reg  = (rl >> 3) + reg_kp;
            const int idx  = ((rowtile * 2 + ks) * 32 + lane) * 4 + reg;
            g_qf_h[idx] = pack_bf16x2(h0, h1);
            g_qf_l[idx] = pack_bf16x2(l0, l1);
        }
    }
}

// ---------------------------------------------------------------------------
// GEMM2 v4 (mma.sync): out = q @ Wd + bd.  CTA tile 128x128, K=32.
// Zero smem, zero syncs: fragments LDG'd fully coalesced from the packed
// fragment arrays (A: LDG.128/lane, B: LDG.64/lane).  Bit-identical inputs.
// ---------------------------------------------------------------------------
__global__ __launch_bounds__(256) void k_gemm2_mma(const float* __restrict__ bd,
                                                   float* __restrict__ out)
{
    const int tid  = threadIdx.x;
    const int lane = tid & 31, wid = tid >> 5;
    const int wm = wid >> 2, wn = wid & 3;
    const int n0 = blockIdx.x * 128;
    const int m0 = blockIdx.y * 128;

    const int lg = lane >> 2;          // fragment row group 0..7
    const int lk = 2 * (lane & 3);     // fragment k offset 0,2,4,6

    float acc[4][4][4];
    #pragma unroll
    for (int im = 0; im < 4; im++)
        #pragma unroll
        for (int in = 0; in < 4; in++)
            #pragma unroll
            for (int j = 0; j < 4; j++) acc[im][in][j] = 0.f;

    #pragma unroll
    for (int ks = 0; ks < 2; ks++) {
        uint4 ah[4], al[4]; uint2 bh[4], bl[4];
        #pragma unroll
        for (int im = 0; im < 4; im++) {
            const int rt  = blockIdx.y * 8 + wm * 4 + im;
            const int idx = ((rt * 2 + ks) * 32 + lane) * 4;
            ah[im] = *(const uint4*)&g_qf_h[idx];
            al[im] = *(const uint4*)&g_qf_l[idx];
        }
        #pragma unroll
        for (int in = 0; in < 4; in++) {
            const int nt  = blockIdx.x * 16 + wn * 4 + in;
            const int idx = ((nt * 2 + ks) * 32 + lane) * 2;
            bh[in] = *(const uint2*)&g_Wdf_h[idx];
            bl[in] = *(const uint2*)&g_Wdf_l[idx];
        }
        #pragma unroll
        for (int im = 0; im < 4; im++)
            #pragma unroll
            for (int in = 0; in < 4; in++) {
                mma16816(acc[im][in], &ah[im].x, &bh[in].x);
                mma16816(acc[im][in], &ah[im].x, &bl[in].x);
                mma16816(acc[im][in], &al[im].x, &bh[in].x);
            }
    }

    // epilogue: + bd -> out  (R14's proven mapping)
    #pragma unroll
    for (int im = 0; im < 4; im++) {
        const int rowa = m0 + wm * 64 + im * 16 + lg;
        #pragma unroll
        for (int in = 0; in < 4; in++) {
            const int col = n0 + wn * 32 + in * 8 + lk;
            const float bb0 = bd[col], bb1 = bd[col + 1];
            float2 v0 = make_float2(acc[im][in][0] + bb0, acc[im][in][1] + bb1);
            float2 v1 = make_float2(acc[im][in][2] + bb0, acc[im][in][3] + bb1);
            *(float2*)&out[(size_t)rowa * IN_DIM + col]       = v0;
            *(float2*)&out[(size_t)(rowa + 8) * IN_DIM + col] = v1;
        }
    }
}

// ---------------------------------------------------------------------------
extern "C" void kernel_launch(void* const* d_in, const int* in_sizes, int n_in,
                              void* d_out, int out_size)
{
    const float* x  = (const float*)d_in[0];
    const float* W1 = (const float*)d_in[1];
    const float* b1 = (const float*)d_in[2];
    const float* W2 = (const float*)d_in[3];
    const float* b2 = (const float*)d_in[4];
    const float* W3 = (const float*)d_in[5];
    const float* b3 = (const float*)d_in[6];
    const float* qp = (const float*)d_in[7];
    const float* Wd = (const float*)d_in[8];
    const float* bd = (const float*)d_in[9];
    float* out = (float*)d_out;

    k_prep<<<dim3(IN_DIM / 32, 5), dim3(32, 8)>>>(W1, Wd);
    k_gemm1_mma<<<BDIM / 128, 256>>>(x, b1);
    k_head<<<BDIM / 64, 256>>>(W2, b2, W3, b3, qp);
    k_gemm2_mma<<<dim3(IN_DIM / 128, BDIM / 128), 256>>>(bd, out);
}

// round 16
// speedup vs baseline: 1.2008x; 1.0946x over previous
#include <cuda_runtime.h>
#include <cuda_bf16.h>
#include <cstdint>
#include <math.h>

#define BDIM   16384
#define IN_DIM 4096
#define H1D    128
#define H2D    64
#define LAT    32
#define NREPS  3
#define SROW   80        // bf16 smem row stride (bytes) for gemm2
#define SROW4  144       // tf32 smem row stride (bytes): 36 floats, conflict-free

// ---------------------------------------------------------------------------
// Scratch (__device__ globals: allocation-free rule)
// ---------------------------------------------------------------------------
__device__ float g_h1[(size_t)BDIM * H1D];                            // 8 MB
__device__ __align__(16) float g_W1t_f[(size_t)H1D * IN_DIM];         // W1^T tf32-rounded, 2 MB
__device__ __align__(16) __nv_bfloat16 g_q_h[(size_t)BDIM * LAT];
__device__ __align__(16) __nv_bfloat16 g_q_l[(size_t)BDIM * LAT];
__device__ __align__(16) __nv_bfloat16 g_Wdt_h[(size_t)IN_DIM * LAT]; // Wd^T [n][k]
__device__ __align__(16) __nv_bfloat16 g_Wdt_l[(size_t)IN_DIM * LAT];

// ---------------------------------------------------------------------------
// Helpers (baseline PTX only: ldmatrix + mma.sync, sm_80-compatible)
// ---------------------------------------------------------------------------
__device__ __forceinline__ uint32_t smem_u32(const void* p) {
    uint32_t a;
    asm("{ .reg .u64 t; cvta.to.shared.u64 t, %1; cvt.u32.u64 %0, t; }" : "=r"(a) : "l"(p));
    return a;
}
__device__ __forceinline__ void ldsm_x4(uint32_t* r, uint32_t addr) {
    asm volatile("ldmatrix.sync.aligned.m8n8.x4.shared.b16 {%0,%1,%2,%3}, [%4];"
                 : "=r"(r[0]), "=r"(r[1]), "=r"(r[2]), "=r"(r[3]) : "r"(addr));
}
__device__ __forceinline__ void ldsm_x2(uint32_t* r, uint32_t addr) {
    asm volatile("ldmatrix.sync.aligned.m8n8.x2.shared.b16 {%0,%1}, [%2];"
                 : "=r"(r[0]), "=r"(r[1]) : "r"(addr));
}
__device__ __forceinline__ void mma16816(float* c, const uint32_t* a, const uint32_t* b) {
    asm volatile("mma.sync.aligned.m16n8k16.row.col.f32.bf16.bf16.f32 "
                 "{%0,%1,%2,%3}, {%4,%5,%6,%7}, {%8,%9}, {%0,%1,%2,%3};"
                 : "+f"(c[0]), "+f"(c[1]), "+f"(c[2]), "+f"(c[3])
                 : "r"(a[0]), "r"(a[1]), "r"(a[2]), "r"(a[3]), "r"(b[0]), "r"(b[1]));
}
__device__ __forceinline__ void mma1688_tf32(float* c, const uint32_t* a, const uint32_t* b) {
    asm volatile("mma.sync.aligned.m16n8k8.row.col.f32.tf32.tf32.f32 "
                 "{%0,%1,%2,%3}, {%4,%5,%6,%7}, {%8,%9}, {%0,%1,%2,%3};"
                 : "+f"(c[0]), "+f"(c[1]), "+f"(c[2]), "+f"(c[3])
                 : "r"(a[0]), "r"(a[1]), "r"(a[2]), "r"(a[3]), "r"(b[0]), "r"(b[1]));
}
__device__ __forceinline__ uint32_t f2tf32(float f) {
    uint32_t r;
    asm("cvt.rna.tf32.f32 %0, %1;" : "=r"(r) : "f"(f));
    return r;
}
__device__ __forceinline__ uint32_t pack_bf16x2(__nv_bfloat16 a, __nv_bfloat16 b) {
    return (uint32_t)__bfloat16_as_ushort(a) | ((uint32_t)__bfloat16_as_ushort(b) << 16);
}
__device__ __forceinline__ void split_bf16(float v, __nv_bfloat16& hi, __nv_bfloat16& lo) {
    hi = __float2bfloat16_rn(v);
    lo = __float2bfloat16_rn(v - __bfloat162float(hi));
}

// ---------------------------------------------------------------------------
// Merged prep: y<4 -> W1^T tf32-rounded float; y==4 -> Wd^T hi/lo bf16 split.
// ---------------------------------------------------------------------------
__global__ void k_prep(const float* __restrict__ W1, const float* __restrict__ Wd) {
    __shared__ float t[32][33];
    const int tx = threadIdx.x, ty = threadIdx.y;   // (32, 8)
    if (blockIdx.y < 4) {
        const int k0 = blockIdx.x * 32, n0 = blockIdx.y * 32;
        #pragma unroll
        for (int i = 0; i < 4; i++)
            t[ty + 8 * i][tx] = W1[(size_t)(k0 + ty + 8 * i) * H1D + n0 + tx];
        __syncthreads();
        #pragma unroll
        for (int i = 0; i < 4; i++) {
            const int n = n0 + ty + 8 * i, k = k0 + tx;
            g_W1t_f[(size_t)n * IN_DIM + k] = __uint_as_float(f2tf32(t[tx][ty + 8 * i]));
        }
    } else {
        const int n0 = blockIdx.x * 32;
        #pragma unroll
        for (int i = 0; i < 4; i++)
            t[ty + 8 * i][tx] = Wd[(size_t)(ty + 8 * i) * IN_DIM + n0 + tx];
        __syncthreads();
        #pragma unroll
        for (int i = 0; i < 4; i++) {
            const int n = n0 + ty + 8 * i, k = tx;
            __nv_bfloat16 h, l;
            split_bf16(t[tx][ty + 8 * i], h, l);
            g_Wdt_h[(size_t)n * LAT + k] = h;
            g_Wdt_l[(size_t)n * LAT + k] = l;
        }
    }
}

// ---------------------------------------------------------------------------
// GEMM1 (tf32 mma.sync): h1 = relu(x @ W1 + b1)
// CTA tile 128x128, BK=32, 8 warps (2x4), warp tile 64x32.
// m16n8k8 tf32: 64 MMAs/warp/iter (vs 96 bf16) -- fewer tensor instructions.
// A/B staged as 32-bit tf32 in smem (row stride 144B, conflict-free), loaded
// with b16 ldmatrix on 16B chunks (layout verified: reg j = m_j[l>>2][l&3]).
// ---------------------------------------------------------------------------
__global__ __launch_bounds__(256) void k_gemm1_mma(const float* __restrict__ x,
                                                   const float* __restrict__ b1)
{
    __shared__ __align__(128) char sm[2 * 128 * SROW4];   // A (18 KB) + B (18 KB)
    char* sA = sm;
    char* sB = sm + 128 * SROW4;
    const uint32_t uA = smem_u32(sA), uB = smem_u32(sB);

    const int tid  = threadIdx.x;
    const int lane = tid & 31, wid = tid >> 5;
    const int wm = wid >> 2, wn = wid & 3;         // warp grid 2(m) x 4(n)
    const int r = tid >> 1, h = tid & 1;           // load role: row, k-half
    const int row0 = blockIdx.x * 128;

    float acc[4][4][4];
    #pragma unroll
    for (int im = 0; im < 4; im++)
        #pragma unroll
        for (int in = 0; in < 4; in++)
            #pragma unroll
            for (int j = 0; j < 4; j++) acc[im][in][j] = 0.f;

    const float* xp = &x[(size_t)(row0 + r) * IN_DIM + h * 16];
    const float* wp = &g_W1t_f[(size_t)r * IN_DIM + h * 16];

    // prefetch iter 0
    float4 xa[4], wa[4];
    #pragma unroll
    for (int j = 0; j < 4; j++) { xa[j] = *(const float4*)(xp + j * 4); wa[j] = *(const float4*)(wp + j * 4); }

    const uint32_t sts = (uint32_t)(r * SROW4 + h * 64);

    // ldmatrix address components
    const int l7  = lane & 7;
    const int l8  = (lane >> 3) & 1;
    const int lhi = lane >> 4;
    // A (x4): row = base + l7 + l8*8, byte = ks4*32 + lhi*16
    const uint32_t aBase = uA + (uint32_t)((wm * 64 + l7 + l8 * 8) * SROW4) + (uint32_t)(lhi * 16);
    // B (x2): row = nbase + l7, byte = ks4*32 + l8*16   (lanes 16-31 unused)
    const uint32_t bBase = uB + (uint32_t)((wn * 32 + l7) * SROW4) + (uint32_t)(l8 * 16);

    for (int i = 0; i < IN_DIM / 32; ++i) {
        // convert x to tf32 + STS; W already tf32-rounded
        {
            uint32_t c0[4], c1[4], c2[4], c3[4];
            c0[0]=f2tf32(xa[0].x); c0[1]=f2tf32(xa[0].y); c0[2]=f2tf32(xa[0].z); c0[3]=f2tf32(xa[0].w);
            c1[0]=f2tf32(xa[1].x); c1[1]=f2tf32(xa[1].y); c1[2]=f2tf32(xa[1].z); c1[3]=f2tf32(xa[1].w);
            c2[0]=f2tf32(xa[2].x); c2[1]=f2tf32(xa[2].y); c2[2]=f2tf32(xa[2].z); c2[3]=f2tf32(xa[2].w);
            c3[0]=f2tf32(xa[3].x); c3[1]=f2tf32(xa[3].y); c3[2]=f2tf32(xa[3].z); c3[3]=f2tf32(xa[3].w);
            *(uint4*)(sA + sts)      = make_uint4(c0[0], c0[1], c0[2], c0[3]);
            *(uint4*)(sA + sts + 16) = make_uint4(c1[0], c1[1], c1[2], c1[3]);
            *(uint4*)(sA + sts + 32) = make_uint4(c2[0], c2[1], c2[2], c2[3]);
            *(uint4*)(sA + sts + 48) = make_uint4(c3[0], c3[1], c3[2], c3[3]);
            *(float4*)(sB + sts)      = wa[0];
            *(float4*)(sB + sts + 16) = wa[1];
            *(float4*)(sB + sts + 32) = wa[2];
            *(float4*)(sB + sts + 48) = wa[3];
        }
        __syncthreads();

        // prefetch next tile (overlaps with ldmatrix/mma below)
        if (i < IN_DIM / 32 - 1) {
            const int off = (i + 1) * 32;
            #pragma unroll
            for (int j = 0; j < 4; j++) {
                xa[j] = *(const float4*)(xp + off + j * 4);
                wa[j] = *(const float4*)(wp + off + j * 4);
            }
        }

        #pragma unroll
        for (int ks = 0; ks < 4; ks++) {            // 4 k8-steps
            uint32_t a[4][4], b[4][2];
            #pragma unroll
            for (int im = 0; im < 4; im++)
                ldsm_x4(a[im], aBase + (uint32_t)(im * 16 * SROW4) + (uint32_t)(ks * 32));
            #pragma unroll
            for (int in = 0; in < 4; in++)
                ldsm_x2(b[in], bBase + (uint32_t)(in * 8 * SROW4) + (uint32_t)(ks * 32));
            #pragma unroll
            for (int im = 0; im < 4; im++)
                #pragma unroll
                for (int in = 0; in < 4; in++)
                    mma1688_tf32(acc[im][in], a[im], b[in]);
        }
        __syncthreads();
    }

    // epilogue: bias + relu -> g_h1 (C layout identical to bf16 m16n8)
    #pragma unroll
    for (int im = 0; im < 4; im++) {
        const int rowa = row0 + wm * 64 + im * 16 + (lane >> 2);
        #pragma unroll
        for (int in = 0; in < 4; in++) {
            const int col = wn * 32 + in * 8 + 2 * (lane & 3);
            const float bb0 = b1[col], bb1 = b1[col + 1];
            float2 v0 = make_float2(fmaxf(acc[im][in][0] + bb0, 0.f),
                                    fmaxf(acc[im][in][1] + bb1, 0.f));
            float2 v1 = make_float2(fmaxf(acc[im][in][2] + bb0, 0.f),
                                    fmaxf(acc[im][in][3] + bb1, 0.f));
            *(float2*)&g_h1[(size_t)rowa * H1D + col]       = v0;
            *(float2*)&g_h1[(size_t)(rowa + 8) * H1D + col] = v1;
        }
    }
}

// ---------------------------------------------------------------------------
// Head v3: j-across-lanes layout (R5, unchanged).
// ---------------------------------------------------------------------------
__global__ __launch_bounds__(256) void k_head(const float* __restrict__ W2,
                                              const float* __restrict__ b2,
                                              const float* __restrict__ W3,
                                              const float* __restrict__ b3,
                                              const float* __restrict__ qparams)
{
    __shared__ float h1s[64][132];
    __shared__ float h2s[64][68];

    const int row0 = blockIdx.x * 64;
    const int tid  = threadIdx.x;

    #pragma unroll
    for (int i = 0; i < 8; i++) {
        const int f = tid + 256 * i;
        const int r = f >> 5, c4 = (f & 31) << 2;
        *(float4*)&h1s[r][c4] = *(const float4*)&g_h1[(size_t)(row0 + r) * H1D + c4];
    }
    __syncthreads();

    {
        const int j  = tid & 63;
        const int rg = tid >> 6;
        float acc[16];
        const float bj = b2[j];
        #pragma unroll
        for (int t = 0; t < 16; t++) acc[t] = bj;

        #pragma unroll 4
        for (int k = 0; k < H1D; k++) {
            const float w = W2[k * H2D + j];
            #pragma unroll
            for (int t = 0; t < 16; t++)
                acc[t] = fmaf(h1s[rg * 16 + t][k], w, acc[t]);
        }
        #pragma unroll
        for (int t = 0; t < 16; t++)
            h2s[rg * 16 + t][j] = fmaxf(acc[t], 0.f);
    }
    __syncthreads();

    {
        const int j2  = tid & 31;
        const int rg2 = tid >> 5;
        float base = b3[j2];
        #pragma unroll
        for (int rep = 0; rep < 2 * NREPS; rep++)
            base += qparams[rep * LAT + j2];

        float z[8];
        #pragma unroll
        for (int t = 0; t < 8; t++) z[t] = base;

        #pragma unroll 4
        for (int k = 0; k < H2D; k++) {
            const float w = W3[k * LAT + j2];
            #pragma unroll
            for (int t = 0; t < 8; t++)
                z[t] = fmaf(h2s[rg2 * 8 + t][k], w, z[t]);
        }

        #pragma unroll
        for (int t = 0; t < 8; t++) {
            const int row = row0 + rg2 * 8 + t;
            const float qv = cosf(z[t]);
            __nv_bfloat16 hh, ll;
            split_bf16(qv, hh, ll);
            g_q_h[(size_t)row * LAT + j2] = hh;
            g_q_l[(size_t)row * LAT + j2] = ll;
        }
    }
}

// ---------------------------------------------------------------------------
// GEMM2 (mma.sync bf16): out = q @ Wd + bd.  CTA tile 128x128, K=32.
// (exact R5 version -- measured 69.8us)
// ---------------------------------------------------------------------------
__global__ __launch_bounds__(256) void k_gemm2_mma(const float* __restrict__ bd,
                                                   float* __restrict__ out)
{
    __shared__ __align__(128) char sm[4 * 128 * SROW];
    char* sQh = sm;
    char* sQl = sm + 128 * SROW;
    char* sWh = sm + 2 * 128 * SROW;
    char* sWl = sm + 3 * 128 * SROW;
    const uint32_t uQh = smem_u32(sQh), uQl = smem_u32(sQl);
    const uint32_t uWh = smem_u32(sWh), uWl = smem_u32(sWl);

    const int tid  = threadIdx.x;
    const int lane = tid & 31, wid = tid >> 5;
    const int wm = wid >> 2, wn = wid & 3;
    const int r = tid >> 1, h = tid & 1;
    const int n0 = blockIdx.x * 128;
    const int m0 = blockIdx.y * 128;

    const uint32_t sts = (uint32_t)(r * SROW + h * 32);
    {
        const __nv_bfloat16* qh = &g_q_h[(size_t)(m0 + r) * LAT + h * 16];
        const __nv_bfloat16* ql = &g_q_l[(size_t)(m0 + r) * LAT + h * 16];
        const __nv_bfloat16* wh = &g_Wdt_h[(size_t)(n0 + r) * LAT + h * 16];
        const __nv_bfloat16* wl = &g_Wdt_l[(size_t)(n0 + r) * LAT + h * 16];
        *(uint4*)(sQh + sts)      = *(const uint4*)qh;
        *(uint4*)(sQh + sts + 16) = *(const uint4*)(qh + 8);
        *(uint4*)(sQl + sts)      = *(const uint4*)ql;
        *(uint4*)(sQl + sts + 16) = *(const uint4*)(ql + 8);
        *(uint4*)(sWh + sts)      = *(const uint4*)wh;
        *(uint4*)(sWh + sts + 16) = *(const uint4*)(wh + 8);
        *(uint4*)(sWl + sts)      = *(const uint4*)wl;
        *(uint4*)(sWl + sts + 16) = *(const uint4*)(wl + 8);
    }
    __syncthreads();

    float acc[4][4][4];
    #pragma unroll
    for (int im = 0; im < 4; im++)
        #pragma unroll
        for (int in = 0; in < 4; in++)
            #pragma unroll
            for (int j = 0; j < 4; j++) acc[im][in][j] = 0.f;

    #pragma unroll
    for (int ks = 0; ks < 2; ks++) {
        uint32_t ah[4][4], al[4][4], bh[4][2], bl[4][2];
        const uint32_t akb = (uint32_t)(ks * 32 + (lane >> 4) * 16 + (lane & 15) * SROW);
        #pragma unroll
        for (int im = 0; im < 4; im++) {
            const uint32_t mo = (uint32_t)((wm * 64 + im * 16) * SROW) + akb;
            ldsm_x4(ah[im], uQh + mo);
            ldsm_x4(al[im], uQl + mo);
        }
        const uint32_t bkb = (uint32_t)(ks * 32 + ((lane >> 3) & 1) * 16 + (lane & 7) * SROW);
        #pragma unroll
        for (int in = 0; in < 4; in++) {
            const uint32_t no = (uint32_t)((wn * 32 + in * 8) * SROW) + bkb;
            ldsm_x2(bh[in], uWh + no);
            ldsm_x2(bl[in], uWl + no);
        }
        #pragma unroll
        for (int im = 0; im < 4; im++)
            #pragma unroll
            for (int in = 0; in < 4; in++) {
                mma16816(acc[im][in], ah[im], bh[in]);
                mma16816(acc[im][in], ah[im], bl[in]);
                mma16816(acc[im][in], al[im], bh[in]);
            }
    }

    // epilogue: + bd -> out
    #pragma unroll
    for (int im = 0; im < 4; im++) {
        const int rowa = m0 + wm * 64 + im * 16 + (lane >> 2);
        #pragma unroll
        for (int in = 0; in < 4; in++) {
            const int col = n0 + wn * 32 + in * 8 + 2 * (lane & 3);
            const float bb0 = bd[col], bb1 = bd[col + 1];
            float2 v0 = make_float2(acc[im][in][0] + bb0, acc[im][in][1] + bb1);
            float2 v1 = make_float2(acc[im][in][2] + bb0, acc[im][in][3] + bb1);
            *(float2*)&out[(size_t)rowa * IN_DIM + col]       = v0;
            *(float2*)&out[(size_t)(rowa + 8) * IN_DIM + col] = v1;
        }
    }
}

// ---------------------------------------------------------------------------
extern "C" void kernel_launch(void* const* d_in, const int* in_sizes, int n_in,
                              void* d_out, int out_size)
{
    const float* x  = (const float*)d_in[0];
    const float* W1 = (const float*)d_in[1];
    const float* b1 = (const float*)d_in[2];
    const float* W2 = (const float*)d_in[3];
    const float* b2 = (const float*)d_in[4];
    const float* W3 = (const float*)d_in[5];
    const float* b3 = (const float*)d_in[6];
    const float* qp = (const float*)d_in[7];
    const float* Wd = (const float*)d_in[8];
    const float* bd = (const float*)d_in[9];
    float* out = (float*)d_out;

    k_prep<<<dim3(IN_DIM / 32, 5), dim3(32, 8)>>>(W1, Wd);
    k_gemm1_mma<<<BDIM / 128, 256>>>(x, b1);
    k_head<<<BDIM / 64, 256>>>(W2, b2, W3, b3, qp);
    k_gemm2_mma<<<dim3(IN_DIM / 128, BDIM / 128), 256>>>(bd, out);
}